// round 7
// baseline (speedup 1.0000x reference)
#include <cuda_runtime.h>
#include <math.h>

#define V_   100000
#define D_   128
#define B_   4096
#define NEG_ 5
#define DI_  170
#define BT_  32
#define NBLK (B_ / BT_)      // 128
#define THREADS 1024

typedef unsigned long long u64;

__device__ __forceinline__ u64 fma2(u64 a, u64 b, u64 c) {
    u64 d;
    asm("fma.rn.f32x2 %0, %1, %2, %3;" : "=l"(d) : "l"(a), "l"(b), "l"(c));
    return d;
}
__device__ __forceinline__ u64 pk2(float lo, float hi) {
    u64 r;
    asm("mov.b64 %0, {%1, %2};" : "=l"(r) : "f"(lo), "f"(hi));
    return r;
}
__device__ __forceinline__ float2 unpk(u64 v) {
    float2 r;
    asm("mov.b64 {%0, %1}, %2;" : "=f"(r.x), "=f"(r.y) : "l"(v));
    return r;
}

// ---- device scratch ----
__device__ float g_partial[NBLK];
__device__ unsigned int g_ticket;

// ------------------------------------------------------------------
// Single fused kernel: 128 blocks x 1024 threads, 32 batch rows/block.
//
// smem layout (bytes):
//   [0, 176800)       whg_s float4[170*65]          (phase-2 weights)
//     after phase 2, region aliased as:
//       wffs  float[128*173]  @0      (88576)       raw Wff rows, pad 173
//       xpart float[4][128*34] @88576 (69632)       phase-3 i-quarter partials
//   [176800, 193184)  emb_i float4[1024]  (idx = d4*32 + k*8 + bg)
//     after phase 3, aliased as x_s[32][128]
//   [193184, 214944)  a_t float[170*32]
//   [214944, 215648)  inv_s float[176]
//   [215648, 215776)  wacc float[32]
//   [215776, 215780)  flag
// ------------------------------------------------------------------
#define OFF_XPART 88576
#define XPART_IQ  4352      // floats per quarter: 128*34
#define SMEM_BYTES 215808

__global__ __launch_bounds__(THREADS) void main_kernel(
    const int*   __restrict__ input_ids,
    const int*   __restrict__ target_ids,
    const int*   __restrict__ neg_ids,
    const float* __restrict__ W_in,
    const float* __restrict__ W_out,
    const float* __restrict__ Wh,
    const float* __restrict__ Wg,
    const float* __restrict__ Wff,
    const float* __restrict__ hs,
    const float* __restrict__ gs,
    const float* __restrict__ logit_scale,
    float*       __restrict__ out)
{
    extern __shared__ __align__(16) char smem[];
    float4* whg_s = (float4*)smem;
    float*  wffs  = (float*)smem;                    // alias after phase 2
    float*  xpart = (float*)(smem + OFF_XPART);      // alias after phase 2
    float4* emb_i = (float4*)(smem + 176800);
    float*  x_s   = (float*)(smem + 176800);         // alias after phase 3
    float*  a_t   = (float*)(smem + 193184);
    float*  inv_s = (float*)(smem + 214944);
    float*  wacc  = (float*)(smem + 215648);
    int*    sflag = (int*)(smem + 215776);

    const int tid  = threadIdx.x;
    const int lane = tid & 31;
    const int warp = tid >> 5;
    const int b0   = blockIdx.x * BT_;

    // ---- Phase 1: gather + l2-normalize 32 input embeddings (1 per warp) ----
    {
        int row = input_ids[b0 + warp];
        float4 v = ((const float4*)(W_in + (size_t)row * D_))[lane];
        float ss = v.x * v.x + v.y * v.y + v.z * v.z + v.w * v.w;
        #pragma unroll
        for (int o = 16; o; o >>= 1) ss += __shfl_xor_sync(0xffffffffu, ss, o);
        float inv = rsqrtf(ss);
        emb_i[lane * 32 + (warp & 3) * 8 + (warp >> 2)] =
            make_float4(v.x * inv, v.y * inv, v.z * inv, v.w * inv);
    }

    // ---- Prefetch phase-4 gather lines into L2 ----
    {
        int gb = b0 + warp;
        if (lane < 24) {
            int j = lane >> 2;
            int row = (j == 0) ? target_ids[gb] : neg_ids[gb * NEG_ + j - 1];
            const float* p = W_out + (size_t)row * D_ + (lane & 3) * 32;
            asm volatile("prefetch.global.L2 [%0];" :: "l"(p));
        } else if (lane < 30) {
            int j = lane - 24;
            int row = (j == 0) ? target_ids[gb] : neg_ids[gb * NEG_ + j - 1];
            const float* p = logit_scale + row;
            asm volatile("prefetch.global.L2 [%0];" :: "l"(p));
        }
    }

    // ---- Stage whg: normalize Wh/Wg rows in-block (340 warp-tasks) ----
    #pragma unroll 1
    for (int t = warp; t < 2 * DI_; t += 32) {
        int mat = (t >= DI_);
        int r   = mat ? (t - DI_) : t;
        const float4* W = (const float4*)(mat ? Wg : Wh);
        float4 v = W[r * 32 + lane];
        float ss = v.x * v.x + v.y * v.y + v.z * v.z + v.w * v.w;
        #pragma unroll
        for (int o = 16; o; o >>= 1) ss += __shfl_xor_sync(0xffffffffu, ss, o);
        float sc = rsqrtf(ss) * (mat ? gs[r] * 11.3137084989847604f : hs[r]);
        whg_s[r * 65 + lane * 2 + mat] =
            make_float4(v.x * sc, v.y * sc, v.z * sc, v.w * sc);
    }
    __syncthreads();

    // ---- Phase 2 (warps 0-21) ∥ Wff column norms from gmem (warps 22-31) ----
    if (tid < 85 * 8) {
        int bg = tid & 7;
        int pp = tid >> 3;              // 0..84 -> rows i0 = 2pp, 2pp+1
        const ulonglong2* w0 = (const ulonglong2*)&whg_s[(2 * pp) * 65];
        const ulonglong2* w1 = (const ulonglong2*)&whg_s[(2 * pp + 1) * 65];
        const ulonglong2* eb = (const ulonglong2*)emb_i;
        u64 h0[4] = {0,0,0,0}, g0[4] = {0,0,0,0};
        u64 h1[4] = {0,0,0,0}, g1[4] = {0,0,0,0};
        #pragma unroll 2
        for (int d4 = 0; d4 < 32; d4++) {
            ulonglong2 wh0 = w0[d4 * 2];
            ulonglong2 wg0 = w0[d4 * 2 + 1];
            ulonglong2 wh1 = w1[d4 * 2];
            ulonglong2 wg1 = w1[d4 * 2 + 1];
            #pragma unroll
            for (int k = 0; k < 4; k++) {
                ulonglong2 ev = eb[d4 * 32 + k * 8 + bg];
                h0[k] = fma2(ev.x, wh0.x, h0[k]);
                h0[k] = fma2(ev.y, wh0.y, h0[k]);
                g0[k] = fma2(ev.x, wg0.x, g0[k]);
                g0[k] = fma2(ev.y, wg0.y, g0[k]);
                h1[k] = fma2(ev.x, wh1.x, h1[k]);
                h1[k] = fma2(ev.y, wh1.y, h1[k]);
                g1[k] = fma2(ev.x, wg1.x, g1[k]);
                g1[k] = fma2(ev.y, wg1.y, g1[k]);
            }
        }
        #pragma unroll
        for (int k = 0; k < 4; k++) {
            float2 hp = unpk(h0[k]); float2 gp = unpk(g0[k]);
            float h = hp.x + hp.y, g = gp.x + gp.y;
            a_t[(2 * pp) * 32 + 4 * bg + k] = h * (g / (1.f + __expf(-g)));
            hp = unpk(h1[k]); gp = unpk(g1[k]);
            h = hp.x + hp.y; g = gp.x + gp.y;
            a_t[(2 * pp + 1) * 32 + 4 * bg + k] = h * (g / (1.f + __expf(-g)));
        }
    } else if (warp >= 22) {
        int c = (warp - 22) * 32 + lane;        // column of Wff
        if (c < DI_) {
            float ss = 0.f;
            #pragma unroll 8
            for (int d = 0; d < D_; d++) {
                float w = Wff[d * DI_ + c];     // coalesced across lanes
                ss += w * w;
            }
            inv_s[c] = rsqrtf(ss);
        }
    }
    __syncthreads();

    // ---- Stage raw Wff rows [d][i] (pad 173, L2-hot) + fold inv into a_t ----
    {
        #pragma unroll
        for (int rr = 0; rr < 4; rr++) {
            int d = warp * 4 + rr;
            #pragma unroll
            for (int k = 0; k < 6; k++) {
                int c = lane + 32 * k;
                if (c < DI_) wffs[d * 173 + c] = Wff[d * DI_ + c];
            }
        }
        #pragma unroll 1
        for (int idx = tid; idx < DI_ * 32; idx += THREADS)
            a_t[idx] *= inv_s[idx >> 5];
    }
    __syncthreads();

    // ---- Phase 3: thread = (d, 16-b half, i-quarter); 8 FFMA2/iter ----
    {
        int d   = tid & 127;
        int grp = tid >> 7;            // 0..7
        int bg  = grp & 1;             // b half: b0 = bg*16
        int iq  = grp >> 1;            // i quarter
        int i0  = iq * 43;
        int ilen = (iq == 3) ? 41 : 43;
        u64 acc[8] = {0,0,0,0,0,0,0,0};
        const float* wrow = wffs + d * 173 + i0;         // lane-distinct banks
        const ulonglong2* ap = (const ulonglong2*)(a_t + i0 * 32 + bg * 16);
        #pragma unroll 1
        for (int it = 0; it < ilen; it++) {
            float w = wrow[it];
            u64 ww = pk2(w, w);
            ulonglong2 a0 = ap[0];     // broadcast LDS.128: b-pairs (b0..b3)
            ulonglong2 a1 = ap[1];
            ulonglong2 a2 = ap[2];
            ulonglong2 a3 = ap[3];
            acc[0] = fma2(a0.x, ww, acc[0]);
            acc[1] = fma2(a0.y, ww, acc[1]);
            acc[2] = fma2(a1.x, ww, acc[2]);
            acc[3] = fma2(a1.y, ww, acc[3]);
            acc[4] = fma2(a2.x, ww, acc[4]);
            acc[5] = fma2(a2.y, ww, acc[5]);
            acc[6] = fma2(a3.x, ww, acc[6]);
            acc[7] = fma2(a3.y, ww, acc[7]);
            ap += 8;
        }
        // store partials: xpart[iq][d*34 + b] (pad 34 keeps 8B alignment)
        float* xp = xpart + iq * XPART_IQ + d * 34 + bg * 16;
        #pragma unroll
        for (int k = 0; k < 8; k++)
            *(u64*)(xp + 2 * k) = acc[k];
    }
    __syncthreads();

    // ---- Reduce i-quarters: x_s[b*128+d] = sum_iq xpart[iq][d*34+b] ----
    #pragma unroll
    for (int r = 0; r < 4; r++) {
        int idx = tid + r * THREADS;       // 4096 outputs
        int b = idx >> 7, d = idx & 127;
        const float* p = xpart + d * 34 + b;
        float s = p[0] + p[XPART_IQ] + p[2 * XPART_IQ] + p[3 * XPART_IQ];
        x_s[b * 128 + d] = s;
    }
    __syncthreads();

    // ---- Phase 4: 6 gathered logits per row; warp = 1 batch row ----
    float local = 0.f;
    {
        int b  = warp;
        int gb = b0 + b;
        int rows[6]; float4 wv[6]; float lsc[6];
        #pragma unroll
        for (int j = 0; j < 6; j++)
            rows[j] = (j == 0) ? target_ids[gb] : neg_ids[gb * NEG_ + (j - 1)];
        #pragma unroll
        for (int j = 0; j < 6; j++)
            wv[j] = ((const float4*)(W_out + (size_t)rows[j] * D_))[lane];
        #pragma unroll
        for (int j = 0; j < 6; j++) lsc[j] = logit_scale[rows[j]];

        float4 x4 = ((const float4*)(x_s + b * 128))[lane];
        #pragma unroll
        for (int j = 0; j < 6; j++) {
            float dot = wv[j].x * x4.x + wv[j].y * x4.y + wv[j].z * x4.z + wv[j].w * x4.w;
            float ss  = wv[j].x * wv[j].x + wv[j].y * wv[j].y + wv[j].z * wv[j].z + wv[j].w * wv[j].w;
            #pragma unroll
            for (int o = 16; o; o >>= 1) {
                dot += __shfl_xor_sync(0xffffffffu, dot, o);
                ss  += __shfl_xor_sync(0xffffffffu, ss, o);
            }
            if (lane == 0) {
                float logit = dot * rsqrtf(ss) * lsc[j] * 11.3137084989847604f;
                float z = (j == 0) ? logit : -logit;
                float ls = fminf(z, 0.f) - log1pf(__expf(-fabsf(z)));
                local += ls * ((j == 0) ? (1.f / B_) : (1.f / (B_ * NEG_)));
            }
        }
    }
    if (lane == 0) wacc[warp] = local;
    __syncthreads();

    // ---- block partial + fused deterministic final reduction ----
    if (tid == 0) {
        float s = 0.f;
        #pragma unroll
        for (int w = 0; w < 32; w++) s += wacc[w];
        g_partial[blockIdx.x] = s;
        __threadfence();
        unsigned int t = atomicAdd(&g_ticket, 1u);
        sflag[0] = (t == NBLK - 1) ? 1 : 0;
    }
    __syncthreads();
    if (sflag[0]) {
        __threadfence();
        float* red = a_t;  // reuse smem
        if (tid < NBLK) red[tid] = g_partial[tid];
        __syncthreads();
        #pragma unroll
        for (int o = NBLK / 2; o; o >>= 1) {
            if (tid < o) red[tid] += red[tid + o];
            __syncthreads();
        }
        if (tid == 0) {
            out[0] = -red[0];
            g_ticket = 0;   // reset for next graph replay
        }
    }
}

extern "C" void kernel_launch(void* const* d_in, const int* in_sizes, int n_in,
                              void* d_out, int out_size)
{
    const int*   input_ids   = (const int*)  d_in[0];
    const int*   target_ids  = (const int*)  d_in[1];
    const int*   neg_ids     = (const int*)  d_in[2];
    const float* W_in        = (const float*)d_in[3];
    const float* W_out       = (const float*)d_in[4];
    const float* W_hidden    = (const float*)d_in[5];
    const float* W_gate      = (const float*)d_in[6];
    const float* W_ff_out    = (const float*)d_in[7];
    const float* hidden_sc   = (const float*)d_in[8];
    const float* gate_sc     = (const float*)d_in[9];
    const float* logit_scale = (const float*)d_in[10];
    float* out = (float*)d_out;

    cudaFuncSetAttribute(main_kernel, cudaFuncAttributeMaxDynamicSharedMemorySize, SMEM_BYTES);

    main_kernel<<<NBLK, THREADS, SMEM_BYTES>>>(input_ids, target_ids, neg_ids,
                                               W_in, W_out, W_hidden, W_gate,
                                               W_ff_out, hidden_sc, gate_sc,
                                               logit_scale, out);
}

// round 8
// speedup vs baseline: 1.0043x; 1.0043x over previous
#include <cuda_runtime.h>
#include <math.h>

#define V_   100000
#define D_   128
#define B_   4096
#define NEG_ 5
#define DI_  170
#define BT_  32
#define NBLK (B_ / BT_)      // 128
#define THREADS 1024

typedef unsigned long long u64;

__device__ __forceinline__ u64 fma2(u64 a, u64 b, u64 c) {
    u64 d;
    asm("fma.rn.f32x2 %0, %1, %2, %3;" : "=l"(d) : "l"(a), "l"(b), "l"(c));
    return d;
}
__device__ __forceinline__ u64 pk2(float lo, float hi) {
    u64 r;
    asm("mov.b64 %0, {%1, %2};" : "=l"(r) : "f"(lo), "f"(hi));
    return r;
}
__device__ __forceinline__ float2 unpk(u64 v) {
    float2 r;
    asm("mov.b64 {%0, %1}, %2;" : "=f"(r.x), "=f"(r.y) : "l"(v));
    return r;
}

// ---- device scratch ----
__device__ float g_partial[NBLK];
__device__ unsigned int g_ticket;

// ------------------------------------------------------------------
// Single fused kernel: 128 blocks x 1024 threads, 32 batch rows/block.
//
// smem layout (bytes):
//   [0, 176800)       whg_s float4[170*65]          (phase-2 weights)
//     after phase 2, region aliased as:
//       wffs  float[128*173]  @0      (88576)       raw Wff rows, pad 173
//       xpart float[4][128*34] @88576 (69632)       phase-3 i-quarter partials
//   [176800, 193184)  emb_i float4[1024]  (idx = d4*32 + k*8 + bg)
//     after phase 3, aliased as x_s[32][128]
//   [193184, 214944)  a_t float[170*32]
//   [214944, 215648)  inv_s float[176]
//   [215648, 215776)  wacc float[32]
//   [215776, 215780)  flag
// ------------------------------------------------------------------
#define OFF_XPART 88576
#define XPART_IQ  4352      // floats per quarter: 128*34
#define SMEM_BYTES 215808

__global__ __launch_bounds__(THREADS) void main_kernel(
    const int*   __restrict__ input_ids,
    const int*   __restrict__ target_ids,
    const int*   __restrict__ neg_ids,
    const float* __restrict__ W_in,
    const float* __restrict__ W_out,
    const float* __restrict__ Wh,
    const float* __restrict__ Wg,
    const float* __restrict__ Wff,
    const float* __restrict__ hs,
    const float* __restrict__ gs,
    const float* __restrict__ logit_scale,
    float*       __restrict__ out)
{
    extern __shared__ __align__(16) char smem[];
    float4* whg_s = (float4*)smem;
    float*  wffs  = (float*)smem;                    // alias after phase 2
    float*  xpart = (float*)(smem + OFF_XPART);      // alias after phase 2
    float4* emb_i = (float4*)(smem + 176800);
    float*  x_s   = (float*)(smem + 176800);         // alias after phase 3
    float*  a_t   = (float*)(smem + 193184);
    float*  inv_s = (float*)(smem + 214944);
    float*  wacc  = (float*)(smem + 215648);
    int*    sflag = (int*)(smem + 215776);

    const int tid  = threadIdx.x;
    const int lane = tid & 31;
    const int warp = tid >> 5;
    const int b0   = blockIdx.x * BT_;

    // ---- Phase 1: gather + l2-normalize 32 input embeddings (1 per warp) ----
    {
        int row = input_ids[b0 + warp];
        float4 v = ((const float4*)(W_in + (size_t)row * D_))[lane];
        float ss = v.x * v.x + v.y * v.y + v.z * v.z + v.w * v.w;
        #pragma unroll
        for (int o = 16; o; o >>= 1) ss += __shfl_xor_sync(0xffffffffu, ss, o);
        float inv = rsqrtf(ss);
        emb_i[lane * 32 + (warp & 3) * 8 + (warp >> 2)] =
            make_float4(v.x * inv, v.y * inv, v.z * inv, v.w * inv);
    }

    // ---- Prefetch phase-4 gather lines into L2 ----
    {
        int gb = b0 + warp;
        if (lane < 24) {
            int j = lane >> 2;
            int row = (j == 0) ? target_ids[gb] : neg_ids[gb * NEG_ + j - 1];
            const float* p = W_out + (size_t)row * D_ + (lane & 3) * 32;
            asm volatile("prefetch.global.L2 [%0];" :: "l"(p));
        } else if (lane < 30) {
            int j = lane - 24;
            int row = (j == 0) ? target_ids[gb] : neg_ids[gb * NEG_ + j - 1];
            const float* p = logit_scale + row;
            asm volatile("prefetch.global.L2 [%0];" :: "l"(p));
        }
    }

    // ---- Stage whg: normalize Wh/Wg rows in-block (340 warp-tasks) ----
    #pragma unroll 1
    for (int t = warp; t < 2 * DI_; t += 32) {
        int mat = (t >= DI_);
        int r   = mat ? (t - DI_) : t;
        const float4* W = (const float4*)(mat ? Wg : Wh);
        float4 v = W[r * 32 + lane];
        float ss = v.x * v.x + v.y * v.y + v.z * v.z + v.w * v.w;
        #pragma unroll
        for (int o = 16; o; o >>= 1) ss += __shfl_xor_sync(0xffffffffu, ss, o);
        float sc = rsqrtf(ss) * (mat ? gs[r] * 11.3137084989847604f : hs[r]);
        whg_s[r * 65 + lane * 2 + mat] =
            make_float4(v.x * sc, v.y * sc, v.z * sc, v.w * sc);
    }
    __syncthreads();

    // ---- Phase 2 (warps 0-21) ∥ Wff column norms from gmem (warps 22-31) ----
    if (tid < 85 * 8) {
        int bg = tid & 7;
        int pp = tid >> 3;              // 0..84 -> rows i0 = 2pp, 2pp+1
        const ulonglong2* w0 = (const ulonglong2*)&whg_s[(2 * pp) * 65];
        const ulonglong2* w1 = (const ulonglong2*)&whg_s[(2 * pp + 1) * 65];
        const ulonglong2* eb = (const ulonglong2*)emb_i;
        u64 h0[4] = {0,0,0,0}, g0[4] = {0,0,0,0};
        u64 h1[4] = {0,0,0,0}, g1[4] = {0,0,0,0};
        #pragma unroll 2
        for (int d4 = 0; d4 < 32; d4++) {
            ulonglong2 wh0 = w0[d4 * 2];
            ulonglong2 wg0 = w0[d4 * 2 + 1];
            ulonglong2 wh1 = w1[d4 * 2];
            ulonglong2 wg1 = w1[d4 * 2 + 1];
            #pragma unroll
            for (int k = 0; k < 4; k++) {
                ulonglong2 ev = eb[d4 * 32 + k * 8 + bg];
                h0[k] = fma2(ev.x, wh0.x, h0[k]);
                h0[k] = fma2(ev.y, wh0.y, h0[k]);
                g0[k] = fma2(ev.x, wg0.x, g0[k]);
                g0[k] = fma2(ev.y, wg0.y, g0[k]);
                h1[k] = fma2(ev.x, wh1.x, h1[k]);
                h1[k] = fma2(ev.y, wh1.y, h1[k]);
                g1[k] = fma2(ev.x, wg1.x, g1[k]);
                g1[k] = fma2(ev.y, wg1.y, g1[k]);
            }
        }
        #pragma unroll
        for (int k = 0; k < 4; k++) {
            float2 hp = unpk(h0[k]); float2 gp = unpk(g0[k]);
            float h = hp.x + hp.y, g = gp.x + gp.y;
            a_t[(2 * pp) * 32 + 4 * bg + k] = h * (g / (1.f + __expf(-g)));
            hp = unpk(h1[k]); gp = unpk(g1[k]);
            h = hp.x + hp.y; g = gp.x + gp.y;
            a_t[(2 * pp + 1) * 32 + 4 * bg + k] = h * (g / (1.f + __expf(-g)));
        }
    } else if (warp >= 22) {
        int c = (warp - 22) * 32 + lane;        // column of Wff
        if (c < DI_) {
            float ss = 0.f;
            #pragma unroll 8
            for (int d = 0; d < D_; d++) {
                float w = Wff[d * DI_ + c];     // coalesced across lanes
                ss += w * w;
            }
            inv_s[c] = rsqrtf(ss);
        }
    }
    __syncthreads();

    // ---- Stage raw Wff rows [d][i] (pad 173, L2-hot) + fold inv into a_t ----
    {
        #pragma unroll
        for (int rr = 0; rr < 4; rr++) {
            int d = warp * 4 + rr;
            #pragma unroll
            for (int k = 0; k < 6; k++) {
                int c = lane + 32 * k;
                if (c < DI_) wffs[d * 173 + c] = Wff[d * DI_ + c];
            }
        }
        #pragma unroll 1
        for (int idx = tid; idx < DI_ * 32; idx += THREADS)
            a_t[idx] *= inv_s[idx >> 5];
    }
    __syncthreads();

    // ---- Phase 3: thread = (d, 16-b half, i-quarter); 8 FFMA2/iter ----
    {
        int d   = tid & 127;
        int grp = tid >> 7;            // 0..7
        int bg  = grp & 1;             // b half: b0 = bg*16
        int iq  = grp >> 1;            // i quarter
        int i0  = iq * 43;
        int ilen = (iq == 3) ? 41 : 43;
        u64 acc[8] = {0,0,0,0,0,0,0,0};
        const float* wrow = wffs + d * 173 + i0;         // lane-distinct banks
        const ulonglong2* ap = (const ulonglong2*)(a_t + i0 * 32 + bg * 16);
        #pragma unroll 1
        for (int it = 0; it < ilen; it++) {
            float w = wrow[it];
            u64 ww = pk2(w, w);
            ulonglong2 a0 = ap[0];     // broadcast LDS.128: b-pairs (b0..b3)
            ulonglong2 a1 = ap[1];
            ulonglong2 a2 = ap[2];
            ulonglong2 a3 = ap[3];
            acc[0] = fma2(a0.x, ww, acc[0]);
            acc[1] = fma2(a0.y, ww, acc[1]);
            acc[2] = fma2(a1.x, ww, acc[2]);
            acc[3] = fma2(a1.y, ww, acc[3]);
            acc[4] = fma2(a2.x, ww, acc[4]);
            acc[5] = fma2(a2.y, ww, acc[5]);
            acc[6] = fma2(a3.x, ww, acc[6]);
            acc[7] = fma2(a3.y, ww, acc[7]);
            ap += 8;
        }
        // store partials: xpart[iq][d*34 + b] (pad 34 keeps 8B alignment)
        float* xp = xpart + iq * XPART_IQ + d * 34 + bg * 16;
        #pragma unroll
        for (int k = 0; k < 8; k++)
            *(u64*)(xp + 2 * k) = acc[k];
    }
    __syncthreads();

    // ---- Reduce i-quarters: x_s[b*128+d] = sum_iq xpart[iq][d*34+b] ----
    #pragma unroll
    for (int r = 0; r < 4; r++) {
        int idx = tid + r * THREADS;       // 4096 outputs
        int b = idx >> 7, d = idx & 127;
        const float* p = xpart + d * 34 + b;
        float s = p[0] + p[XPART_IQ] + p[2 * XPART_IQ] + p[3 * XPART_IQ];
        x_s[b * 128 + d] = s;
    }
    __syncthreads();

    // ---- Phase 4: 6 gathered logits per row; warp = 1 batch row ----
    float local = 0.f;
    {
        int b  = warp;
        int gb = b0 + b;
        int rows[6]; float4 wv[6]; float lsc[6];
        #pragma unroll
        for (int j = 0; j < 6; j++)
            rows[j] = (j == 0) ? target_ids[gb] : neg_ids[gb * NEG_ + (j - 1)];
        #pragma unroll
        for (int j = 0; j < 6; j++)
            wv[j] = ((const float4*)(W_out + (size_t)rows[j] * D_))[lane];
        #pragma unroll
        for (int j = 0; j < 6; j++) lsc[j] = logit_scale[rows[j]];

        float4 x4 = ((const float4*)(x_s + b * 128))[lane];
        #pragma unroll
        for (int j = 0; j < 6; j++) {
            float dot = wv[j].x * x4.x + wv[j].y * x4.y + wv[j].z * x4.z + wv[j].w * x4.w;
            float ss  = wv[j].x * wv[j].x + wv[j].y * wv[j].y + wv[j].z * wv[j].z + wv[j].w * wv[j].w;
            #pragma unroll
            for (int o = 16; o; o >>= 1) {
                dot += __shfl_xor_sync(0xffffffffu, dot, o);
                ss  += __shfl_xor_sync(0xffffffffu, ss, o);
            }
            if (lane == 0) {
                float logit = dot * rsqrtf(ss) * lsc[j] * 11.3137084989847604f;
                float z = (j == 0) ? logit : -logit;
                float ls = fminf(z, 0.f) - log1pf(__expf(-fabsf(z)));
                local += ls * ((j == 0) ? (1.f / B_) : (1.f / (B_ * NEG_)));
            }
        }
    }
    if (lane == 0) wacc[warp] = local;
    __syncthreads();

    // ---- block partial + fused deterministic final reduction ----
    if (tid == 0) {
        float s = 0.f;
        #pragma unroll
        for (int w = 0; w < 32; w++) s += wacc[w];
        g_partial[blockIdx.x] = s;
        __threadfence();
        unsigned int t = atomicAdd(&g_ticket, 1u);
        sflag[0] = (t == NBLK - 1) ? 1 : 0;
    }
    __syncthreads();
    if (sflag[0]) {
        __threadfence();
        float* red = a_t;  // reuse smem
        if (tid < NBLK) red[tid] = g_partial[tid];
        __syncthreads();
        #pragma unroll
        for (int o = NBLK / 2; o; o >>= 1) {
            if (tid < o) red[tid] += red[tid + o];
            __syncthreads();
        }
        if (tid == 0) {
            out[0] = -red[0];
            g_ticket = 0;   // reset for next graph replay
        }
    }
}

extern "C" void kernel_launch(void* const* d_in, const int* in_sizes, int n_in,
                              void* d_out, int out_size)
{
    const int*   input_ids   = (const int*)  d_in[0];
    const int*   target_ids  = (const int*)  d_in[1];
    const int*   neg_ids     = (const int*)  d_in[2];
    const float* W_in        = (const float*)d_in[3];
    const float* W_out       = (const float*)d_in[4];
    const float* W_hidden    = (const float*)d_in[5];
    const float* W_gate      = (const float*)d_in[6];
    const float* W_ff_out    = (const float*)d_in[7];
    const float* hidden_sc   = (const float*)d_in[8];
    const float* gate_sc     = (const float*)d_in[9];
    const float* logit_scale = (const float*)d_in[10];
    float* out = (float*)d_out;

    cudaFuncSetAttribute(main_kernel, cudaFuncAttributeMaxDynamicSharedMemorySize, SMEM_BYTES);

    main_kernel<<<NBLK, THREADS, SMEM_BYTES>>>(input_ids, target_ids, neg_ids,
                                               W_in, W_out, W_hidden, W_gate,
                                               W_ff_out, hidden_sc, gate_sc,
                                               logit_scale, out);
}

// round 9
// speedup vs baseline: 1.0069x; 1.0026x over previous
#include <cuda_runtime.h>
#include <math.h>

#define V_   100000
#define D_   128
#define B_   4096
#define NEG_ 5
#define DI_  170
#define BT_  32
#define NBLK (B_ / BT_)      // 128
#define THREADS 1024

typedef unsigned long long u64;

__device__ __forceinline__ u64 fma2(u64 a, u64 b, u64 c) {
    u64 d;
    asm("fma.rn.f32x2 %0, %1, %2, %3;" : "=l"(d) : "l"(a), "l"(b), "l"(c));
    return d;
}
__device__ __forceinline__ u64 pk2(float lo, float hi) {
    u64 r;
    asm("mov.b64 %0, {%1, %2};" : "=l"(r) : "f"(lo), "f"(hi));
    return r;
}
__device__ __forceinline__ float2 unpk(u64 v) {
    float2 r;
    asm("mov.b64 {%0, %1}, %2;" : "=f"(r.x), "=f"(r.y) : "l"(v));
    return r;
}

// ---- device scratch ----
__device__ float g_partial[NBLK];
__device__ unsigned int g_ticket;

// ------------------------------------------------------------------
// Single fused kernel: 128 blocks x 1024 threads, 32 batch rows/block.
//
// smem layout (bytes):
//   [0, 176800)       whg_s float4[170*65]          (phase-2 weights)
//     after phase 2, region aliased as:
//       wffs  float[128*177]   @0      (90624)      Wff rows * inv[c], pad 177
//       xpart float[4][128*34] @90624  (69632)      phase-3 i-quarter partials
//   [176800, 193184)  emb_i float4[1024]  (idx = d4*32 + k*8 + bg)
//     after phase 3, aliased as x_s[32][128]
//   [193184, 215712)  a_t float[176*32]   (rows 170-175 zeroed)
//   [215712, 216416)  inv_s float[176]
//   [216416, 216544)  wacc float[32]
//   [216544, 216548)  flag
// ------------------------------------------------------------------
#define WFF_STRIDE 177
#define OFF_XPART  90624
#define XPART_IQ   4352      // floats per quarter: 128*34
#define SMEM_BYTES 216576

__global__ __launch_bounds__(THREADS) void main_kernel(
    const int*   __restrict__ input_ids,
    const int*   __restrict__ target_ids,
    const int*   __restrict__ neg_ids,
    const float* __restrict__ W_in,
    const float* __restrict__ W_out,
    const float* __restrict__ Wh,
    const float* __restrict__ Wg,
    const float* __restrict__ Wff,
    const float* __restrict__ hs,
    const float* __restrict__ gs,
    const float* __restrict__ logit_scale,
    float*       __restrict__ out)
{
    extern __shared__ __align__(16) char smem[];
    float4* whg_s = (float4*)smem;
    float*  wffs  = (float*)smem;                    // alias after phase 2
    float*  xpart = (float*)(smem + OFF_XPART);      // alias after phase 2
    float4* emb_i = (float4*)(smem + 176800);
    float*  x_s   = (float*)(smem + 176800);         // alias after phase 3
    float*  a_t   = (float*)(smem + 193184);
    float*  inv_s = (float*)(smem + 215712);
    float*  wacc  = (float*)(smem + 216416);
    int*    sflag = (int*)(smem + 216544);

    const int tid  = threadIdx.x;
    const int lane = tid & 31;
    const int warp = tid >> 5;
    const int b0   = blockIdx.x * BT_;

    // ---- Phase 1: gather + l2-normalize 32 input embeddings (1 per warp) ----
    {
        int row = input_ids[b0 + warp];
        float4 v = ((const float4*)(W_in + (size_t)row * D_))[lane];
        float ss = v.x * v.x + v.y * v.y + v.z * v.z + v.w * v.w;
        #pragma unroll
        for (int o = 16; o; o >>= 1) ss += __shfl_xor_sync(0xffffffffu, ss, o);
        float inv = rsqrtf(ss);
        emb_i[lane * 32 + (warp & 3) * 8 + (warp >> 2)] =
            make_float4(v.x * inv, v.y * inv, v.z * inv, v.w * inv);
    }

    // ---- Prefetch phase-4 gather lines into L2 ----
    {
        int gb = b0 + warp;
        if (lane < 24) {
            int j = lane >> 2;
            int row = (j == 0) ? target_ids[gb] : neg_ids[gb * NEG_ + j - 1];
            const float* p = W_out + (size_t)row * D_ + (lane & 3) * 32;
            asm volatile("prefetch.global.L2 [%0];" :: "l"(p));
        } else if (lane < 30) {
            int j = lane - 24;
            int row = (j == 0) ? target_ids[gb] : neg_ids[gb * NEG_ + j - 1];
            const float* p = logit_scale + row;
            asm volatile("prefetch.global.L2 [%0];" :: "l"(p));
        }
    }

    // ---- Stage whg: normalize Wh/Wg rows in-block (340 warp-tasks) ----
    #pragma unroll 1
    for (int t = warp; t < 2 * DI_; t += 32) {
        int mat = (t >= DI_);
        int r   = mat ? (t - DI_) : t;
        const float4* W = (const float4*)(mat ? Wg : Wh);
        float4 v = W[r * 32 + lane];
        float ss = v.x * v.x + v.y * v.y + v.z * v.z + v.w * v.w;
        #pragma unroll
        for (int o = 16; o; o >>= 1) ss += __shfl_xor_sync(0xffffffffu, ss, o);
        float sc = rsqrtf(ss) * (mat ? gs[r] * 11.3137084989847604f : hs[r]);
        whg_s[r * 65 + lane * 2 + mat] =
            make_float4(v.x * sc, v.y * sc, v.z * sc, v.w * sc);
    }
    __syncthreads();

    // ---- Phase 2 (warps 0-21) ∥ Wff column norms (warps 22+) + a_t pad zero ----
    if (tid < 85 * 8) {
        int bg = tid & 7;
        int pp = tid >> 3;              // 0..84 -> rows i0 = 2pp, 2pp+1
        const ulonglong2* w0 = (const ulonglong2*)&whg_s[(2 * pp) * 65];
        const ulonglong2* w1 = (const ulonglong2*)&whg_s[(2 * pp + 1) * 65];
        const ulonglong2* eb = (const ulonglong2*)emb_i;
        u64 h0[4] = {0,0,0,0}, g0[4] = {0,0,0,0};
        u64 h1[4] = {0,0,0,0}, g1[4] = {0,0,0,0};
        #pragma unroll 2
        for (int d4 = 0; d4 < 32; d4++) {
            ulonglong2 wh0 = w0[d4 * 2];
            ulonglong2 wg0 = w0[d4 * 2 + 1];
            ulonglong2 wh1 = w1[d4 * 2];
            ulonglong2 wg1 = w1[d4 * 2 + 1];
            #pragma unroll
            for (int k = 0; k < 4; k++) {
                ulonglong2 ev = eb[d4 * 32 + k * 8 + bg];
                h0[k] = fma2(ev.x, wh0.x, h0[k]);
                h0[k] = fma2(ev.y, wh0.y, h0[k]);
                g0[k] = fma2(ev.x, wg0.x, g0[k]);
                g0[k] = fma2(ev.y, wg0.y, g0[k]);
                h1[k] = fma2(ev.x, wh1.x, h1[k]);
                h1[k] = fma2(ev.y, wh1.y, h1[k]);
                g1[k] = fma2(ev.x, wg1.x, g1[k]);
                g1[k] = fma2(ev.y, wg1.y, g1[k]);
            }
        }
        #pragma unroll
        for (int k = 0; k < 4; k++) {
            float2 hp = unpk(h0[k]); float2 gp = unpk(g0[k]);
            float h = hp.x + hp.y, g = gp.x + gp.y;
            a_t[(2 * pp) * 32 + 4 * bg + k] = h * (g / (1.f + __expf(-g)));
            hp = unpk(h1[k]); gp = unpk(g1[k]);
            h = hp.x + hp.y; g = gp.x + gp.y;
            a_t[(2 * pp + 1) * 32 + 4 * bg + k] = h * (g / (1.f + __expf(-g)));
        }
    } else {
        if (warp >= 22) {
            int c = (warp - 22) * 32 + lane;        // column of Wff
            if (c < DI_) {
                float ss = 0.f;
                #pragma unroll 8
                for (int d = 0; d < D_; d++) {
                    float w = Wff[d * DI_ + c];     // coalesced across lanes
                    ss += w * w;
                }
                inv_s[c] = rsqrtf(ss);
            }
        }
        if (tid >= 832)                              // 192 threads: zero pad rows
            a_t[DI_ * 32 + (tid - 832)] = 0.f;
    }
    __syncthreads();

    // ---- Stage wffs[d][c] = Wff[d][c] * inv[c]  (pad cols 170..176 = 0) ----
    {
        #pragma unroll
        for (int rr = 0; rr < 4; rr++) {
            int d = warp * 4 + rr;
            #pragma unroll
            for (int k = 0; k < 6; k++) {
                int c = lane + 32 * k;
                if (c < DI_)
                    wffs[d * WFF_STRIDE + c] = Wff[d * DI_ + c] * inv_s[c];
                else if (c < WFF_STRIDE)
                    wffs[d * WFF_STRIDE + c] = 0.f;
            }
        }
    }
    __syncthreads();

    // ---- Phase 3: thread = (d, 16-b half, i-quarter of 44); unroll 2 ----
    {
        int d   = tid & 127;
        int grp = tid >> 7;            // 0..7
        int bg  = grp & 1;             // b half: b0 = bg*16
        int iq  = grp >> 1;            // i quarter (44 each, padded)
        int i0  = iq * 44;
        u64 acc[8] = {0,0,0,0,0,0,0,0};
        const float* wrow = wffs + d * WFF_STRIDE + i0;
        const ulonglong2* ap = (const ulonglong2*)(a_t + i0 * 32 + bg * 16);
        #pragma unroll 1
        for (int it = 0; it < 44; it += 2) {
            float wA = wrow[it];
            float wB = wrow[it + 1];
            ulonglong2 a0 = ap[0];
            ulonglong2 a1 = ap[1];
            ulonglong2 a2 = ap[2];
            ulonglong2 a3 = ap[3];
            ulonglong2 b0v = ap[8];
            ulonglong2 b1v = ap[9];
            ulonglong2 b2v = ap[10];
            ulonglong2 b3v = ap[11];
            u64 wwA = pk2(wA, wA);
            u64 wwB = pk2(wB, wB);
            acc[0] = fma2(a0.x, wwA, acc[0]);
            acc[1] = fma2(a0.y, wwA, acc[1]);
            acc[2] = fma2(a1.x, wwA, acc[2]);
            acc[3] = fma2(a1.y, wwA, acc[3]);
            acc[4] = fma2(a2.x, wwA, acc[4]);
            acc[5] = fma2(a2.y, wwA, acc[5]);
            acc[6] = fma2(a3.x, wwA, acc[6]);
            acc[7] = fma2(a3.y, wwA, acc[7]);
            acc[0] = fma2(b0v.x, wwB, acc[0]);
            acc[1] = fma2(b0v.y, wwB, acc[1]);
            acc[2] = fma2(b1v.x, wwB, acc[2]);
            acc[3] = fma2(b1v.y, wwB, acc[3]);
            acc[4] = fma2(b2v.x, wwB, acc[4]);
            acc[5] = fma2(b2v.y, wwB, acc[5]);
            acc[6] = fma2(b3v.x, wwB, acc[6]);
            acc[7] = fma2(b3v.y, wwB, acc[7]);
            ap += 16;
        }
        float* xp = xpart + iq * XPART_IQ + d * 34 + bg * 16;
        #pragma unroll
        for (int k = 0; k < 8; k++)
            *(u64*)(xp + 2 * k) = acc[k];
    }

    // ---- Phase-4 gathers issued NOW (x-independent; hide under reduce) ----
    int   rows4[6];
    float4 wv[6];
    float  lsc[6];
    {
        int gb = b0 + warp;
        #pragma unroll
        for (int j = 0; j < 6; j++)
            rows4[j] = (j == 0) ? target_ids[gb] : neg_ids[gb * NEG_ + (j - 1)];
        #pragma unroll
        for (int j = 0; j < 6; j++)
            wv[j] = ((const float4*)(W_out + (size_t)rows4[j] * D_))[lane];
        #pragma unroll
        for (int j = 0; j < 6; j++) lsc[j] = logit_scale[rows4[j]];
    }
    __syncthreads();

    // ---- Reduce i-quarters: x_s[b*128+d] = sum_iq xpart[iq][d*34+b] ----
    #pragma unroll
    for (int r = 0; r < 4; r++) {
        int idx = tid + r * THREADS;       // 4096 outputs
        int b = idx >> 7, d = idx & 127;
        const float* p = xpart + d * 34 + b;
        float s = p[0] + p[XPART_IQ] + p[2 * XPART_IQ] + p[3 * XPART_IQ];
        x_s[b * 128 + d] = s;
    }
    __syncthreads();

    // ---- Phase 4: 6 logits per row; warp = 1 batch row ----
    float local = 0.f;
    {
        float4 x4 = ((const float4*)(x_s + warp * 128))[lane];
        #pragma unroll
        for (int j = 0; j < 6; j++) {
            float dot = wv[j].x * x4.x + wv[j].y * x4.y + wv[j].z * x4.z + wv[j].w * x4.w;
            float ss  = wv[j].x * wv[j].x + wv[j].y * wv[j].y + wv[j].z * wv[j].z + wv[j].w * wv[j].w;
            #pragma unroll
            for (int o = 16; o; o >>= 1) {
                dot += __shfl_xor_sync(0xffffffffu, dot, o);
                ss  += __shfl_xor_sync(0xffffffffu, ss, o);
            }
            if (lane == 0) {
                float logit = dot * rsqrtf(ss) * lsc[j] * 11.3137084989847604f;
                float z = (j == 0) ? logit : -logit;
                float ls = fminf(z, 0.f) - log1pf(__expf(-fabsf(z)));
                local += ls * ((j == 0) ? (1.f / B_) : (1.f / (B_ * NEG_)));
            }
        }
    }
    if (lane == 0) wacc[warp] = local;
    __syncthreads();

    // ---- block partial + fused deterministic final reduction ----
    if (tid == 0) {
        float s = 0.f;
        #pragma unroll
        for (int w = 0; w < 32; w++) s += wacc[w];
        g_partial[blockIdx.x] = s;
        __threadfence();
        unsigned int t = atomicAdd(&g_ticket, 1u);
        sflag[0] = (t == NBLK - 1) ? 1 : 0;
    }
    __syncthreads();
    if (sflag[0]) {
        __threadfence();
        float* red = a_t;  // reuse smem
        if (tid < NBLK) red[tid] = g_partial[tid];
        __syncthreads();
        #pragma unroll
        for (int o = NBLK / 2; o; o >>= 1) {
            if (tid < o) red[tid] += red[tid + o];
            __syncthreads();
        }
        if (tid == 0) {
            out[0] = -red[0];
            g_ticket = 0;   // reset for next graph replay
        }
    }
}

extern "C" void kernel_launch(void* const* d_in, const int* in_sizes, int n_in,
                              void* d_out, int out_size)
{
    const int*   input_ids   = (const int*)  d_in[0];
    const int*   target_ids  = (const int*)  d_in[1];
    const int*   neg_ids     = (const int*)  d_in[2];
    const float* W_in        = (const float*)d_in[3];
    const float* W_out       = (const float*)d_in[4];
    const float* W_hidden    = (const float*)d_in[5];
    const float* W_gate      = (const float*)d_in[6];
    const float* W_ff_out    = (const float*)d_in[7];
    const float* hidden_sc   = (const float*)d_in[8];
    const float* gate_sc     = (const float*)d_in[9];
    const float* logit_scale = (const float*)d_in[10];
    float* out = (float*)d_out;

    cudaFuncSetAttribute(main_kernel, cudaFuncAttributeMaxDynamicSharedMemorySize, SMEM_BYTES);

    main_kernel<<<NBLK, THREADS, SMEM_BYTES>>>(input_ids, target_ids, neg_ids,
                                               W_in, W_out, W_hidden, W_gate,
                                               W_ff_out, hidden_sc, gate_sc,
                                               logit_scale, out);
}